// round 15
// baseline (speedup 1.0000x reference)
#include <cuda_runtime.h>
#include <math.h>

// SparseDimAttention, GB300 sm_103a — mega (single x DRAM read + L2 re-read, lean select)
// + PDL-overlapped head.
// Select: classify from registers, warp-ballot compaction, expf ONLY on selected (~512/4096).

constexpr int Ll = 33, Dd = 4096, Pp = 64, Kk = 512, Hh = 128, Bb = 512;
constexpr int BINS = 1024;

__device__ float g_y[(size_t)Bb * Ll];

__device__ __forceinline__ unsigned int fkey(float f) {
    unsigned int u = __float_as_uint(f);
    return u ^ ((u & 0x80000000u) ? 0xFFFFFFFFu : 0x80000000u); // ascending monotonic
}

#define NTM 512
constexpr int BPTM = BINS / NTM;   // 2
constexpr int SMEM_BYTES = 128 * 1024;  // forces 1 CTA/SM

__global__ void __launch_bounds__(NTM, 1) mega_kernel(
    const float* __restrict__ x, const float* __restrict__ Wp,
    const float* __restrict__ bp, const float* __restrict__ ws,
    const float* __restrict__ bsc)
{
    extern __shared__ float dyn[];
    float* sc    = dyn;                      // [4096] scores (read-only after ph1)
    float* wb    = dyn + Dd;                 // [4096] weights (zeroed, scatter-written)
    int*   hist  = (int*)(wb + Dd);          // [1024] counts -> suffix -> tie list
    int*   slist = hist + BINS;              // [512] selected (sure) indices

    __shared__ float v[Ll];
    __shared__ float redmx[16], redmn[16], redf[16];
    __shared__ int   wsum_[16];
    __shared__ float s_c, s_m, s_lo, s_scale, s_invZ;
    __shared__ int   s_thr, s_rem, s_cnt, s_nsel, s_T;

    const int b = blockIdx.x, tid = threadIdx.x;
    const int lane = tid & 31, wid = tid >> 5;
    const unsigned lmlt = (1u << lane) - 1u;

    if (tid < Ll) {
        float a = 0.f;
        #pragma unroll
        for (int p = 0; p < Pp; ++p) a = fmaf(ws[p], Wp[p * Ll + tid], a);
        v[tid] = a;
    } else if (tid == Ll) {
        float a = bsc[0];
        #pragma unroll
        for (int p = 0; p < Pp; ++p) a = fmaf(ws[p], bp[p], a);
        s_c = a;
    }
    #pragma unroll
    for (int j = 0; j < BPTM; ++j) hist[j * NTM + tid] = 0;
    if (tid == 0) { s_cnt = 0; s_nsel = 0; }
    __syncthreads();

    const float4* __restrict__ xb4 =
        reinterpret_cast<const float4*>(x) + (size_t)b * Ll * (Dd / 4);

    // ---- phase 1: stream x[b] from DRAM; scores kept in regs AND stored to smem ----
    float4 a0, a1;
    {
        const float cc = s_c;
        a0 = make_float4(cc, cc, cc, cc);
        a1 = make_float4(cc, cc, cc, cc);
        #pragma unroll 4
        for (int l = 0; l < Ll; ++l) {
            const float vl = v[l];
            const float4* row = xb4 + (size_t)l * (Dd / 4);
            float4 x0 = row[tid];
            float4 x1 = row[tid + NTM];
            a0.x = fmaf(vl, x0.x, a0.x); a0.y = fmaf(vl, x0.y, a0.y);
            a0.z = fmaf(vl, x0.z, a0.z); a0.w = fmaf(vl, x0.w, a0.w);
            a1.x = fmaf(vl, x1.x, a1.x); a1.y = fmaf(vl, x1.y, a1.y);
            a1.z = fmaf(vl, x1.z, a1.z); a1.w = fmaf(vl, x1.w, a1.w);
        }
        float4* sc4 = reinterpret_cast<float4*>(sc);
        sc4[tid] = a0;
        sc4[tid + NTM] = a1;
        // zero wb while stores are in flight
        float4 z4 = make_float4(0.f, 0.f, 0.f, 0.f);
        float4* wb4 = reinterpret_cast<float4*>(wb);
        wb4[tid] = z4;
        wb4[tid + NTM] = z4;

        float mx = fmaxf(fmaxf(a0.x, a0.y), fmaxf(a0.z, a0.w));
        mx = fmaxf(mx, fmaxf(fmaxf(a1.x, a1.y), fmaxf(a1.z, a1.w)));
        float mn = fminf(fminf(a0.x, a0.y), fminf(a0.z, a0.w));
        mn = fminf(mn, fminf(fminf(a1.x, a1.y), fminf(a1.z, a1.w)));
        #pragma unroll
        for (int o = 16; o > 0; o >>= 1) {
            mx = fmaxf(mx, __shfl_xor_sync(0xFFFFFFFFu, mx, o));
            mn = fminf(mn, __shfl_xor_sync(0xFFFFFFFFu, mn, o));
        }
        if (lane == 0) { redmx[wid] = mx; redmn[wid] = mn; }
    }
    __syncthreads();
    if (tid < 16) {
        float mx = redmx[tid], mn = redmn[tid];
        #pragma unroll
        for (int o = 8; o > 0; o >>= 1) {
            mx = fmaxf(mx, __shfl_xor_sync(0x0000FFFFu, mx, o));
            mn = fminf(mn, __shfl_xor_sync(0x0000FFFFu, mn, o));
        }
        if (tid == 0) {
            s_m = mx; s_lo = mn;
            const float r = mx - mn;
            s_scale = (r > 0.f) ? ((float)(BINS - 1) / r) : 0.f;
        }
    }
    __syncthreads();

    const float lo = s_lo, scale = s_scale, mm = s_m;

    // scores and indices owned by this thread (from registers)
    float w8[8] = {a0.x, a0.y, a0.z, a0.w, a1.x, a1.y, a1.z, a1.w};
    int bins8[8];
    #pragma unroll
    for (int j = 0; j < 8; ++j) {
        int bn = (int)((w8[j] - lo) * scale);
        bins8[j] = min(BINS - 1, max(0, bn));
    }
    // d8(j) = 4*tid + j for j<4 ; 2048 + 4*tid + (j-4) for j>=4

    // histogram from registers
    #pragma unroll
    for (int j = 0; j < 8; ++j) atomicAdd(&hist[bins8[j]], 1);
    __syncthreads();

    // suffix scan: hist[i] = #elements with bin >= i
    {
        const int base = tid * BPTM;
        int c[BPTM];
        #pragma unroll
        for (int j = 0; j < BPTM; ++j) c[j] = hist[base + j];
        #pragma unroll
        for (int j = BPTM - 2; j >= 0; --j) c[j] += c[j + 1];
        int inc = c[0];
        #pragma unroll
        for (int o = 1; o < 32; o <<= 1) {
            int t = __shfl_up_sync(0xFFFFFFFFu, inc, o);
            if (lane >= o) inc += t;
        }
        if (lane == 31) wsum_[wid] = inc;
        __syncthreads();
        if (tid < 16) {
            int w = wsum_[tid];
            int iw = w;
            #pragma unroll
            for (int o = 1; o < 16; o <<= 1) {
                int t = __shfl_up_sync(0x0000FFFFu, iw, o);
                if (tid >= o) iw += t;
            }
            wsum_[tid] = iw - w;
            if (tid == 15) s_T = iw;
        }
        __syncthreads();
        const int S = s_T - (wsum_[wid] + inc);
        #pragma unroll
        for (int j = 0; j < BPTM; ++j) hist[base + j] = S + c[j];
    }
    __syncthreads();

    // threshold bin: hist[i] >= K && hist[i+1] < K
    #pragma unroll
    for (int j = 0; j < BPTM; ++j) {
        const int i = tid * BPTM + j;
        const int hv = hist[i];
        const int nx = (i < BINS - 1) ? hist[i + 1] : 0;
        if (hv >= Kk && nx < Kk) { s_thr = i; s_rem = Kk - nx; }
    }
    __syncthreads();
    const int thr = s_thr, rem = s_rem;

    // build selected list (bins > thr) + tie list (bins == thr), warp-aggregated.
    // hist is reused as the tie list after this barrier region.
    __syncthreads();
    #pragma unroll
    for (int j = 0; j < 8; ++j) {
        const int d = (j < 4) ? (4 * tid + j) : (2048 + 4 * tid + (j - 4));
        const bool sel = (bins8[j] > thr);
        const bool tie = (bins8[j] == thr);
        const unsigned ms = __ballot_sync(0xFFFFFFFFu, sel);
        const unsigned mt = __ballot_sync(0xFFFFFFFFu, tie);
        int bs = 0, bt = 0;
        if (lane == 0) {
            if (ms) bs = atomicAdd(&s_nsel, (int)__popc(ms));
            if (mt) bt = atomicAdd(&s_cnt, (int)__popc(mt));
        }
        bs = __shfl_sync(0xFFFFFFFFu, bs, 0);
        bt = __shfl_sync(0xFFFFFFFFu, bt, 0);
        if (sel) slist[bs + __popc(ms & lmlt)] = d;
        if (tie) {
            const int p = bt + __popc(mt & lmlt);
            if (p < BINS) hist[p] = d;
        }
    }
    __syncthreads();
    const int nsel = s_nsel, cnt = s_cnt;
    const bool fast = (cnt <= BINS);

    // weights: expf ONLY for winners (wb pre-zeroed)
    float zp = 0.f;
    for (int i = tid; i < nsel; i += NTM) {
        const int d = slist[i];
        const float wv = expf(sc[d] - mm);
        wb[d] = wv; zp += wv;
    }
    if (fast) {
        // rank ties by (key desc, idx asc); winners get expf
        for (int i = tid; i < cnt; i += NTM) {
            const int d = hist[i];
            const unsigned int ke = fkey(sc[d]);
            int rank = 0;
            for (int j2 = 0; j2 < cnt; ++j2) {
                const int d2 = hist[j2];
                const unsigned int k2 = fkey(sc[d2]);
                rank += (k2 > ke) || (k2 == ke && d2 < d);
            }
            if (rank < rem) {
                const float wv = expf(sc[d] - mm);
                wb[d] = wv; zp += wv;
            }
        }
    } else {
        // exact fallback (degenerate data): full-scan rank for own tie elements
        #pragma unroll
        for (int j = 0; j < 8; ++j) {
            if (bins8[j] == thr) {
                const int d = (j < 4) ? (4 * tid + j) : (2048 + 4 * tid + (j - 4));
                const unsigned int ke = fkey(w8[j]);
                int rank = 0;
                for (int d2 = 0; d2 < Dd; ++d2) {
                    const float s2 = sc[d2];
                    int b2i = (int)((s2 - lo) * scale);
                    b2i = min(BINS - 1, max(0, b2i));
                    if (b2i == thr) {
                        const unsigned int k2 = fkey(s2);
                        rank += (k2 > ke) || (k2 == ke && d2 < d);
                    }
                }
                if (rank < rem) {
                    const float wv = expf(w8[j] - mm);
                    wb[d] = wv; zp += wv;
                }
            }
        }
    }
    #pragma unroll
    for (int o = 16; o > 0; o >>= 1) zp += __shfl_xor_sync(0xFFFFFFFFu, zp, o);
    if (lane == 0) redf[wid] = zp;
    __syncthreads();
    if (tid < 16) {
        zp = redf[tid];
        #pragma unroll
        for (int o = 8; o > 0; o >>= 1) zp += __shfl_xor_sync(0x0000FFFFu, zp, o);
        if (tid == 0) s_invZ = 1.f / zp;
    }
    __syncthreads();

    // ---- phase 5: y[l] = invZ * sum_d wb[d]*x[b,l,d]  (x[b] re-read from L2) ----
    {
        const float invZ = s_invZ;
        const float4* wb4 = reinterpret_cast<const float4*>(wb);
        for (int l = wid; l < Ll; l += 16) {
            const float4* __restrict__ row = xb4 + (size_t)l * (Dd / 4);
            float a0s = 0.f, a1s = 0.f, a2s = 0.f, a3s = 0.f;
            #pragma unroll 4
            for (int i = lane; i < Dd / 4; i += 32) {
                float4 wv = wb4[i];
                float4 xv = row[i];
                a0s = fmaf(wv.x, xv.x, a0s);
                a1s = fmaf(wv.y, xv.y, a1s);
                a2s = fmaf(wv.z, xv.z, a2s);
                a3s = fmaf(wv.w, xv.w, a3s);
            }
            float acc = (a0s + a1s) + (a2s + a3s);
            #pragma unroll
            for (int o = 16; o > 0; o >>= 1) acc += __shfl_xor_sync(0xFFFFFFFFu, acc, o);
            if (lane == 0) g_y[(size_t)b * Ll + l] = acc * invZ;
        }
    }
}

// ---------------- head: PDL-overlapped, one CTA per batch ----------------
__global__ void __launch_bounds__(128) head_kernel(
    const float* __restrict__ Wp, const float* __restrict__ bp,
    const float* __restrict__ gamma, const float* __restrict__ beta,
    const float* __restrict__ W1, const float* __restrict__ b1,
    const float* __restrict__ W2, const float* __restrict__ b2,
    float* __restrict__ out)
{
    __shared__ float sW1p[Hh * (Pp + 1)];   // padded stride 65 -> conflict-free compute
    __shared__ float sWp[Pp * Ll];          // stride 33 (odd) -> conflict-free compute
    __shared__ float sbp[Pp], sg[Pp], sbe[Pp], sb1[Hh], sW2[2 * Hh], sb2v[2];
    __shared__ float yv[Ll], zz[Pp], aa[Hh];
    __shared__ float s_mu, s_rstd;
    const int b = blockIdx.x;
    const int tid = threadIdx.x;
    const int lane = tid & 31, wid = tid >> 5;

    // ======== PRE-SYNC: stage all weights (overlaps mega's last wave) ========
    {
        const float4* W14 = reinterpret_cast<const float4*>(W1);
        #pragma unroll
        for (int i = tid; i < Hh * Pp / 4; i += 128) {
            float4 w = W14[i];
            const int h = i >> 4, q = i & 15;
            const int base = h * (Pp + 1) + q * 4;
            sW1p[base] = w.x; sW1p[base + 1] = w.y; sW1p[base + 2] = w.z; sW1p[base + 3] = w.w;
        }
    }
    for (int i = tid; i < Pp * Ll; i += 128) sWp[i] = Wp[i];
    if (tid < Pp) { sbp[tid] = bp[tid]; sg[tid] = gamma[tid]; sbe[tid] = beta[tid]; }
    if (tid < Hh) sb1[tid] = b1[tid];
    #pragma unroll
    for (int k = 0; k < 2; ++k) sW2[k * 128 + tid] = W2[k * 128 + tid];
    if (tid < 2) sb2v[tid] = b2[tid];

    // ======== wait for mega's g_y writes ========
    cudaGridDependencySynchronize();

    if (tid < Ll) yv[tid] = g_y[(size_t)b * Ll + tid];   // L2-hot
    __syncthreads();

    if (tid < Pp) {
        float acc = sbp[tid];
        #pragma unroll
        for (int l = 0; l < Ll; ++l) acc = fmaf(sWp[tid * Ll + l], yv[l], acc);
        zz[tid] = acc;
    }
    __syncthreads();

    if (tid < 32) {
        float a = zz[tid], bq = zz[tid + 32];
        float sum = a + bq;
        #pragma unroll
        for (int o = 16; o > 0; o >>= 1) sum += __shfl_xor_sync(0xFFFFFFFFu, sum, o);
        const float mu = sum * (1.f / 64.f);
        const float da = a - mu, db = bq - mu;
        float sq = da * da + db * db;
        #pragma unroll
        for (int o = 16; o > 0; o >>= 1) sq += __shfl_xor_sync(0xFFFFFFFFu, sq, o);
        if (tid == 0) { s_mu = mu; s_rstd = rsqrtf(sq * (1.f / 64.f) + 1e-5f); }
    }
    __syncthreads();
    if (tid < Pp) zz[tid] = (zz[tid] - s_mu) * s_rstd * sg[tid] + sbe[tid];
    __syncthreads();

    {
        float acc = sb1[tid];
        #pragma unroll
        for (int p = 0; p < Pp; ++p)
            acc = fmaf(sW1p[tid * (Pp + 1) + p], zz[p], acc);
        aa[tid] = 0.5f * acc * (1.f + erff(acc * 0.70710678118654752f)); // exact GELU
    }
    __syncthreads();

    if (wid < 2) {
        float acc = 0.f;
        #pragma unroll
        for (int k = 0; k < 4; ++k) {
            const int j = k * 32 + lane;
            acc = fmaf(sW2[wid * Hh + j], aa[j], acc);
        }
        #pragma unroll
        for (int o = 16; o > 0; o >>= 1) acc += __shfl_xor_sync(0xFFFFFFFFu, acc, o);
        if (lane == 0) out[b * 2 + wid] = acc + sb2v[wid];
    }
}

extern "C" void kernel_launch(void* const* d_in, const int* in_sizes, int n_in,
                              void* d_out, int out_size) {
    const float* x     = (const float*)d_in[0];
    const float* Wp    = (const float*)d_in[1];
    const float* bp    = (const float*)d_in[2];
    const float* ws    = (const float*)d_in[3];
    const float* bsc   = (const float*)d_in[4];
    const float* gamma = (const float*)d_in[5];
    const float* beta  = (const float*)d_in[6];
    const float* W1    = (const float*)d_in[7];
    const float* b1    = (const float*)d_in[8];
    const float* W2    = (const float*)d_in[9];
    const float* b2    = (const float*)d_in[10];
    float* out = (float*)d_out;

    cudaFuncSetAttribute(mega_kernel, cudaFuncAttributeMaxDynamicSharedMemorySize, SMEM_BYTES);
    mega_kernel<<<Bb, NTM, SMEM_BYTES>>>(x, Wp, bp, ws, bsc);

    // PDL: head launches while mega drains; gridDependencySync orders g_y access.
    cudaLaunchConfig_t cfg = {};
    cfg.gridDim = dim3(Bb);
    cfg.blockDim = dim3(128);
    cfg.dynamicSmemBytes = 0;
    cfg.stream = 0;
    cudaLaunchAttribute attr[1];
    attr[0].id = cudaLaunchAttributeProgrammaticStreamSerialization;
    attr[0].val.programmaticStreamSerializationAllowed = 1;
    cfg.attrs = attr;
    cfg.numAttrs = 1;
    cudaLaunchKernelEx(&cfg, head_kernel, Wp, bp, gamma, beta, W1, b1, W2, b2, out);
}